// round 2
// baseline (speedup 1.0000x reference)
#include <cuda_runtime.h>
#include <math.h>

#define NN 32
#define KK 16
#define BINS 100
#define TT 99
#define JITTER 1e-5
#define LDA 101   // padded leading dim (odd in doubles -> conflict-free column walks)

// ---- device scratch (no runtime allocation allowed) ----
__device__ double g_A[BINS * BINS];      // A1 = RBF(centers) + J*I
__device__ double g_W[NN * KK];          // orthonormal eigenbasis of QQ^T (n,m)
__device__ double g_z[BINS * KK * 2];    // z[b][m][d]
__device__ double g_s2[KK];              // eigenvalues of Q^T Q
__device__ double g_sig2;
__device__ double g_xlast[NN * 2];
__device__ double g_y[KK * BINS * 2];    // y[m][b][d]
__device__ double g_w[BINS * NN * 2];    // w = QQ^T u, [b][n][d]
__device__ double g_xt[TT * NN * 2];     // xt[t][n][d]

// ===========================================================================
// K1: build A1, G = Q^T Q, Jacobi eigen of G (parallel Brent-Luk), W, z, x_last
// ===========================================================================
__global__ void k_prep(const float* __restrict__ x0, const float* __restrict__ v,
                       const float* __restrict__ sigma_p, const float* __restrict__ ls_p,
                       const float* __restrict__ Q_p) {
    __shared__ double sG[16][16];
    __shared__ double sV[16][16];
    __shared__ double sQ[32][16];
    __shared__ double sW[32][16];
    __shared__ double sC[8], sS[8];
    __shared__ int sP[8], sQn[8];
    __shared__ int arr[16];

    int tid = threadIdx.x;
    double ls = (double)ls_p[0];
    double inv2ls2 = 0.5 / (ls * ls);

    // A1 (independent of Jacobi) -> global
    for (int idx = tid; idx < BINS * BINS; idx += blockDim.x) {
        int i = idx / BINS, j = idx % BINS;
        double d = (double)(j - i) * 0.01;     // center spacing = 1/100
        double a = exp(-d * d * inv2ls2);
        if (i == j) a += JITTER;
        g_A[idx] = a;
    }

    if (tid < 512) sQ[tid >> 4][tid & 15] = (double)Q_p[tid];
    if (tid == 0) {
        double s = (double)sigma_p[0];
        if (s < 0.05) s = 0.05;                // clip(prior_sigma, 5/BINS)
        g_sig2 = s * s;
        for (int i = 0; i < 16; ++i) arr[i] = i;
    }
    __syncthreads();

    if (tid < 256) {
        int i = tid >> 4, j = tid & 15;
        double acc = 0.0;
        for (int n = 0; n < 32; ++n) acc += sQ[n][i] * sQ[n][j];
        sG[i][j] = acc;
        sV[i][j] = (i == j) ? 1.0 : 0.0;
    }
    __syncthreads();

    // cyclic Jacobi, round-robin schedule: 15 rounds x 8 disjoint pairs, 10 sweeps
    for (int sweep = 0; sweep < 10; ++sweep) {
        for (int round = 0; round < 15; ++round) {
            if (tid < 8) {
                int p = arr[tid], q = arr[15 - tid];
                if (p > q) { int t = p; p = q; q = t; }
                sP[tid] = p; sQn[tid] = q;
                double apq = sG[p][q];
                double c = 1.0, s = 0.0;
                if (fabs(apq) > 1e-300) {
                    double tau = (sG[q][q] - sG[p][p]) / (2.0 * apq);
                    double t2 = (tau >= 0.0 ? 1.0 : -1.0) / (fabs(tau) + sqrt(1.0 + tau * tau));
                    c = 1.0 / sqrt(1.0 + t2 * t2);
                    s = t2 * c;
                }
                sC[tid] = c; sS[tid] = s;
            }
            __syncthreads();
            if (tid < 128) {                       // column phase on G
                int r = tid >> 4, i = tid & 15;
                int p = sP[r], q = sQn[r]; double c = sC[r], s = sS[r];
                double gp = sG[i][p], gq = sG[i][q];
                sG[i][p] = c * gp - s * gq; sG[i][q] = s * gp + c * gq;
            } else if (tid < 256) {                // V <- V*J (independent array)
                int r = (tid - 128) >> 4, i = (tid - 128) & 15;
                int p = sP[r], q = sQn[r]; double c = sC[r], s = sS[r];
                double gp = sV[i][p], gq = sV[i][q];
                sV[i][p] = c * gp - s * gq; sV[i][q] = s * gp + c * gq;
            }
            __syncthreads();
            if (tid < 128) {                       // row phase on G
                int r = tid >> 4, i = tid & 15;
                int p = sP[r], q = sQn[r]; double c = sC[r], s = sS[r];
                double gp = sG[p][i], gq = sG[q][i];
                sG[p][i] = c * gp - s * gq; sG[q][i] = s * gp + c * gq;
            }
            __syncthreads();
            if (tid == 0) {                        // rotate schedule (keep arr[0])
                int last = arr[15];
                for (int i = 15; i > 1; --i) arr[i] = arr[i - 1];
                arr[1] = last;
            }
            __syncthreads();
        }
    }

    if (tid < 16) {
        double e = sG[tid][tid];
        g_s2[tid] = (e > 0.0) ? e : 0.0;
    }
    __syncthreads();

    // W = Q * V * S^-1  (orthonormal columns; eigvecs of QQ^T)
    if (tid < 512) {
        int n = tid >> 4, m = tid & 15;
        double acc = 0.0;
        for (int k = 0; k < 16; ++k) acc += sQ[n][k] * sV[k][m];
        double e = sG[m][m]; if (e < 1e-30) e = 1e-30;
        double w = acc / sqrt(e);
        sW[n][m] = w;
        g_W[tid] = w;
    }
    __syncthreads();

    // z[b][m][d] = sum_n W[n][m] * v[b][n][d]
    for (int o = tid; o < BINS * KK * 2; o += blockDim.x) {
        int b = o >> 5;
        int rem = o & 31;
        int m = rem >> 1, d = rem & 1;
        const float* vb = v + b * 64;
        double acc = 0.0;
        for (int n = 0; n < 32; ++n) acc += sW[n][m] * (double)vb[n * 2 + d];
        g_z[o] = acc;
    }

    // x_last = x0 + (1/BINS) * sum_b v
    if (tid < 64) {
        double acc = 0.0;
        for (int b = 0; b < BINS; ++b) acc += (double)v[b * 64 + tid];
        g_xlast[tid] = (double)x0[tid] + 0.01 * acc;
    }
}

// ===========================================================================
// K2: per-mode Cholesky of (sigma^2 I + s2_m A1), solve 2 RHS. 16 blocks.
// ===========================================================================
__global__ void k_chol() {
    extern __shared__ double sm[];
    double* M = sm;                       // 100 x LDA
    double* invD = sm + BINS * LDA;       // 100
    double* yv = invD + BINS;             // 100 x 2

    int tid = threadIdx.x;
    int m = blockIdx.x;
    double s2 = g_s2[m];
    double sig2 = g_sig2;

    for (int idx = tid; idx < BINS * BINS; idx += blockDim.x) {
        int i = idx / BINS, j = idx % BINS;
        double val = s2 * g_A[idx];
        if (i == j) val += sig2;
        M[i * LDA + j] = val;
    }
    for (int t2 = tid; t2 < BINS * 2; t2 += blockDim.x)
        yv[t2] = g_z[(t2 >> 1) * 32 + m * 2 + (t2 & 1)];
    __syncthreads();

    // right-looking Cholesky (lower), diag kept as 1/sqrt in invD
    for (int k = 0; k < BINS; ++k) {
        if (tid == 0) invD[k] = 1.0 / sqrt(M[k * LDA + k]);
        __syncthreads();
        double idk = invD[k];
        for (int i = k + 1 + tid; i < BINS; i += blockDim.x) M[i * LDA + k] *= idk;
        __syncthreads();
        int ty = tid >> 4, tx = tid & 15;
        for (int j = k + 1 + ty; j < BINS; j += 8) {
            double ljk = M[j * LDA + k];
            for (int i = j + tx; i < BINS; i += 16)
                M[i * LDA + j] -= M[i * LDA + k] * ljk;
        }
        __syncthreads();
    }

    // forward solve L y = z (2 RHS)
    for (int k = 0; k < BINS; ++k) {
        if (tid < 2) yv[k * 2 + tid] *= invD[k];
        __syncthreads();
        for (int t2 = tid; t2 < (BINS - 1 - k) * 2; t2 += blockDim.x) {
            int i = k + 1 + (t2 >> 1), d = t2 & 1;
            yv[i * 2 + d] -= M[i * LDA + k] * yv[k * 2 + d];
        }
        __syncthreads();
    }
    // backward solve L^T x = y
    for (int k = BINS - 1; k >= 0; --k) {
        if (tid < 2) yv[k * 2 + tid] *= invD[k];
        __syncthreads();
        for (int t2 = tid; t2 < k * 2; t2 += blockDim.x) {
            int i = t2 >> 1, d = t2 & 1;
            yv[i * 2 + d] -= M[k * LDA + i] * yv[k * 2 + d];
        }
        __syncthreads();
    }
    for (int t2 = tid; t2 < BINS * 2; t2 += blockDim.x)
        g_y[m * BINS * 2 + t2] = yv[t2];
}

// ===========================================================================
// K3: u = v/sig2 + W(y - z/sig2);  w = Q (Q^T u). one block per bin b.
// ===========================================================================
__global__ void k_uw(const float* __restrict__ v, const float* __restrict__ Q_p) {
    __shared__ double sQ[32][16];
    __shared__ double sWl[32][16];
    __shared__ double sc[32];   // (y - z/sig2)[m][d]
    __shared__ double su[64];
    __shared__ double st[32];

    int tid = threadIdx.x;     // 64 threads: n*2+d
    int b = blockIdx.x;
    double isig2 = 1.0 / g_sig2;

    for (int i = tid; i < 512; i += 64) {
        sQ[i >> 4][i & 15] = (double)Q_p[i];
        sWl[i >> 4][i & 15] = g_W[i];
    }
    if (tid < 32) {
        int m = tid >> 1, d = tid & 1;
        sc[tid] = g_y[m * 200 + b * 2 + d] - g_z[b * 32 + m * 2 + d] * isig2;
    }
    __syncthreads();
    {
        int n = tid >> 1, d = tid & 1;
        double acc = (double)v[b * 64 + tid] * isig2;
        for (int m = 0; m < 16; ++m) acc += sWl[n][m] * sc[m * 2 + d];
        su[tid] = acc;
    }
    __syncthreads();
    if (tid < 32) {
        int k = tid >> 1, d = tid & 1;
        double acc = 0.0;
        for (int n = 0; n < 32; ++n) acc += sQ[n][k] * su[n * 2 + d];
        st[tid] = acc;
    }
    __syncthreads();
    {
        int n = tid >> 1, d = tid & 1;
        double acc = 0.0;
        for (int k = 0; k < 16; ++k) acc += sQ[n][k] * st[k * 2 + d];
        g_w[b * 64 + tid] = acc;
    }
}

// ===========================================================================
// K4: pred_v[t] = sum_b RBF(ts[t],c_b) * w[b];  xt[t] = x_last + (ts[t]-1)*pred_v
// ===========================================================================
__global__ void k_pred(const float* __restrict__ ls_p) {
    __shared__ double sB[BINS];
    int tid = threadIdx.x;   // 128 threads
    int t = blockIdx.x;
    double ls = (double)ls_p[0];
    double inv2ls2 = 0.5 / (ls * ls);
    double dt_off = (double)t / 99.0;          // ts[t] - 1
    double tt = 1.0 + dt_off;

    for (int b = tid; b < BINS; b += blockDim.x) {
        double d = tt - ((double)b + 0.5) * 0.01;
        sB[b] = exp(-d * d * inv2ls2);
    }
    __syncthreads();
    if (tid < 64) {
        double acc = 0.0;
        for (int b = 0; b < BINS; ++b) acc += sB[b] * g_w[b * 64 + tid];
        g_xt[t * 64 + tid] = g_xlast[tid] + dt_off * acc;
    }
}

// ===========================================================================
// K5: lambda[n][m] = dt * sum_t exp(beta_n + beta_m - dist_t(n,m))
// ===========================================================================
__global__ void k_lam(const float* __restrict__ beta_p, float* __restrict__ out) {
    __shared__ double sb[32];
    int tid = threadIdx.x;
    int p = blockIdx.x * blockDim.x + tid;     // 8 blocks x 128 = 1024 pairs
    if (tid < 32) sb[tid] = (double)beta_p[tid];
    __syncthreads();
    int n = p >> 5, mc = p & 31;
    double bsum = sb[n] + sb[mc];
    const double2* xt2 = (const double2*)g_xt;
    double acc = 0.0;
    for (int t = 0; t < TT; ++t) {
        double2 a = xt2[t * 32 + n];
        double2 c = xt2[t * 32 + mc];
        double dx = a.x - c.x, dy = a.y - c.y;
        double sq = dx * dx + dy * dy;
        if (sq < 1e-12) sq = 1e-12;
        acc += exp(bsum - sqrt(sq));
    }
    out[p] = (float)(acc * (1.0 / 99.0));
}

extern "C" void kernel_launch(void* const* d_in, const int* in_sizes, int n_in,
                              void* d_out, int out_size) {
    const float* x0    = (const float*)d_in[0];
    const float* v     = (const float*)d_in[1];
    const float* beta  = (const float*)d_in[2];
    const float* sigma = (const float*)d_in[3];
    // d_in[4] = prior_B_x0_c: only touches the x0 block, which provably never
    // reaches the output (B_cross row 0 is zero, Bk is block-diagonal).
    const float* ls    = (const float*)d_in[5];
    const float* Q     = (const float*)d_in[6];
    float* out = (float*)d_out;

    const int chol_smem = (BINS * LDA + BINS + BINS * 2) * (int)sizeof(double);
    cudaFuncSetAttribute(k_chol, cudaFuncAttributeMaxDynamicSharedMemorySize, chol_smem);

    k_prep<<<1, 512>>>(x0, v, sigma, ls, Q);
    k_chol<<<16, 128, chol_smem>>>();
    k_uw<<<BINS, 64>>>(v, Q);
    k_pred<<<TT, 128>>>(ls);
    k_lam<<<8, 128>>>(beta, out);
}

// round 10
// speedup vs baseline: 2.0777x; 2.0777x over previous
#include <cuda_runtime.h>
#include <math.h>

#define NN 32
#define KK 16
#define BINS 100
#define TT 99
#define LDA 101   // padded leading dim: 101 doubles -> conflict-free column walks

// ---- device scratch ----
__device__ double g_T[BINS];            // Toeplitz row of A1 (no jitter)
__device__ double g_W[NN * KK];         // orthonormal eigenbasis of QQ^T
__device__ double g_z[BINS * KK * 2];   // z[b][m][d]
__device__ double g_s2[KK];             // eigenvalues of Q^T Q
__device__ double g_sig2;
__device__ double g_xlast[NN * 2];
__device__ double g_y[KK * BINS * 2];   // y[m][b][d]
__device__ float  g_wf[BINS * NN * 2];  // w = QQ^T u (fp32 for the tail)
__device__ float  g_xtf[TT * NN * 2];   // xt[t][n][d] fp32

// fp64 rsqrt: fp32 seed + 1 fp64 Newton -> rel err ~2e-8 (avoids 1400-cyc sqrt+div chain)
__device__ __forceinline__ double drsqrt1(double x) {
    double y = (double)rsqrtf((float)x);
    y = y * fma(-0.5 * x * y, y, 1.5);
    return y;
}

// ===========================================================================
// K1: Toeplitz row of A1, G = Q^T Q, Jacobi eigen (static schedule, fast c/s),
//     W, z, x_last.  256 threads, 1 block.
// ===========================================================================
__global__ void k_prep(const float* __restrict__ x0, const float* __restrict__ v,
                       const float* __restrict__ sigma_p, const float* __restrict__ ls_p,
                       const float* __restrict__ Q_p) {
    __shared__ double sG[16][17];
    __shared__ double sV[16][17];
    __shared__ double sQ[32][17];
    __shared__ double sW[32][17];
    __shared__ double sC[8], sS[8];
    __shared__ int sP[8], sQn[8];

    int tid = threadIdx.x;     // 256
    double ls = (double)ls_p[0];
    double inv2ls2 = 0.5 / (ls * ls);

    if (tid < BINS) {
        double d = (double)tid * 0.01;     // center spacing
        g_T[tid] = exp(-d * d * inv2ls2);
    }
    for (int i = tid; i < 512; i += 256) sQ[i >> 4][i & 15] = (double)Q_p[i];
    if (tid == 0) {
        double s = (double)sigma_p[0];
        if (s < 0.05) s = 0.05;
        g_sig2 = s * s;
    }
    __syncthreads();

    {   // G = Q^T Q, V = I
        int i = tid >> 4, j = tid & 15;
        double acc = 0.0;
        for (int n = 0; n < 32; ++n) acc += sQ[n][i] * sQ[n][j];
        sG[i][j] = acc;
        sV[i][j] = (i == j) ? 1.0 : 0.0;
    }
    __syncthreads();

    // cyclic Jacobi: static round-robin schedule, 7 sweeps x 15 rounds x 8 pairs
    for (int sweep = 0; sweep < 7; ++sweep) {
        for (int r = 0; r < 15; ++r) {
            if (tid < 8) {
                int p, q;
                if (tid == 0) { p = 15; q = r; }
                else { p = (r + tid) % 15; q = (r + 15 - tid) % 15; }
                if (p > q) { int t = p; p = q; q = t; }
                sP[tid] = p; sQn[tid] = q;
                double app = sG[p][p], aqq = sG[q][q], apq = sG[p][q];
                double c = 1.0, s = 0.0;
                if (fabs(apq) > 1e-25) {
                    // angle in fp32 (self-correcting), orthogonality in fp64
                    float tauf = __fdividef((float)(aqq - app), 2.0f * (float)apq);
                    float tf = copysignf(1.0f, tauf) /
                               (fabsf(tauf) + sqrtf(fmaf(tauf, tauf, 1.0f)));
                    double t = (double)tf;
                    c = drsqrt1(fma(t, t, 1.0));
                    s = t * c;
                }
                sC[tid] = c; sS[tid] = s;
            }
            __syncthreads();
            if (tid < 128) {                       // column rotation on G
                int rr = tid >> 4, i = tid & 15;
                int p = sP[rr], q = sQn[rr]; double c = sC[rr], s = sS[rr];
                double gp = sG[i][p], gq = sG[i][q];
                sG[i][p] = c * gp - s * gq; sG[i][q] = s * gp + c * gq;
            } else {                               // V <- V*J (independent)
                int rr = (tid - 128) >> 4, i = (tid - 128) & 15;
                int p = sP[rr], q = sQn[rr]; double c = sC[rr], s = sS[rr];
                double gp = sV[i][p], gq = sV[i][q];
                sV[i][p] = c * gp - s * gq; sV[i][q] = s * gp + c * gq;
            }
            __syncthreads();
            if (tid < 128) {                       // row rotation on G
                int rr = tid >> 4, i = tid & 15;
                int p = sP[rr], q = sQn[rr]; double c = sC[rr], s = sS[rr];
                double gp = sG[p][i], gq = sG[q][i];
                sG[p][i] = c * gp - s * gq; sG[q][i] = s * gp + c * gq;
            }
            __syncthreads();
        }
    }

    if (tid < 16) {
        double e = sG[tid][tid];
        g_s2[tid] = (e > 0.0) ? e : 0.0;
    }

    // W = Q * V * S^-1
    for (int o = tid; o < 512; o += 256) {
        int n = o >> 4, m = o & 15;
        double acc = 0.0;
        for (int k = 0; k < 16; ++k) acc += sQ[n][k] * sV[k][m];
        double e = sG[m][m]; if (e < 1e-30) e = 1e-30;
        double w = acc * drsqrt1(e);
        sW[n][m] = w;
        g_W[o] = w;
    }
    __syncthreads();

    // z[b][m][d] = sum_n W[n][m] * v[b][n][d]
    for (int o = tid; o < BINS * KK * 2; o += 256) {
        int b = o >> 5, rem = o & 31, m = rem >> 1, d = rem & 1;
        const float* vb = v + b * 64;
        double acc = 0.0;
        for (int n = 0; n < 32; ++n) acc += sW[n][m] * (double)vb[n * 2 + d];
        g_z[o] = acc;
    }

    // x_last = x0 + (1/BINS) * sum_b v
    if (tid < 64) {
        double acc = 0.0;
        for (int b = 0; b < BINS; ++b) acc += (double)v[b * 64 + tid];
        g_xlast[tid] = (double)x0[tid] + 0.01 * acc;
    }
}

// ===========================================================================
// K2: per-mode Cholesky of (sigma^2 I + s2_m A1), warp-sync triangular solves.
// ===========================================================================
__global__ void k_chol() {
    extern __shared__ double sm[];
    double* M    = sm;                  // 100 x 101
    double* invD = sm + BINS * LDA;     // 100
    double* y0   = invD + BINS;         // 100
    double* y1   = y0 + BINS;           // 100
    __shared__ double sT[BINS];

    int tid = threadIdx.x;              // 128
    int m = blockIdx.x;
    double s2 = g_s2[m];
    double sig2 = g_sig2;

    if (tid < BINS) sT[tid] = g_T[tid];
    __syncthreads();
    double dval = s2 * (sT[0] + 1e-5) + sig2;   // jitter folded into diagonal
    for (int idx = tid; idx < BINS * BINS; idx += 128) {
        int i = idx / BINS, j = idx - i * BINS;
        int dd = i - j; if (dd < 0) dd = -dd;
        M[i * LDA + j] = (dd == 0) ? dval : s2 * sT[dd];
    }
    if (tid < BINS) {
        y0[tid] = g_z[tid * 32 + m * 2];
        y1[tid] = g_z[tid * 32 + m * 2 + 1];
    }
    __syncthreads();

    // right-looking Cholesky; rsqrt computed redundantly by all threads (no serialization)
    for (int k = 0; k < BINS; ++k) {
        double idk = drsqrt1(M[k * LDA + k]);
        if (tid == 0) invD[k] = idk;
        for (int i = k + 1 + tid; i < BINS; i += 128) M[i * LDA + k] *= idk;
        __syncthreads();
        int ty = tid >> 4, tx = tid & 15;
        for (int j = k + 1 + ty; j < BINS; j += 8) {
            double ljk = M[j * LDA + k];
            for (int i = j + tx; i < BINS; i += 16)
                M[i * LDA + j] = fma(-M[i * LDA + k], ljk, M[i * LDA + j]);
        }
        __syncthreads();
    }

    // warp-synchronous solves: warp 0 -> d=0, warp 1 -> d=1
    int w = tid >> 5, lane = tid & 31;
    if (w < 2) {
        double* y = (w == 0) ? y0 : y1;
        for (int k = 0; k < BINS; ++k) {           // forward: L y = z
            double yk = y[k] * invD[k];
            __syncwarp();
            if (lane == 0) y[k] = yk;
            for (int i = k + 1 + lane; i < BINS; i += 32)
                y[i] = fma(-M[i * LDA + k], yk, y[i]);
            __syncwarp();
        }
        for (int k = BINS - 1; k >= 0; --k) {      // backward: L^T x = y
            double yk = y[k] * invD[k];
            __syncwarp();
            if (lane == 0) y[k] = yk;
            for (int i = lane; i < k; i += 32)
                y[i] = fma(-M[k * LDA + i], yk, y[i]);
            __syncwarp();
        }
    }
    __syncthreads();
    for (int t2 = tid; t2 < BINS; t2 += 128) {
        g_y[m * 200 + t2 * 2]     = y0[t2];
        g_y[m * 200 + t2 * 2 + 1] = y1[t2];
    }
}

// ===========================================================================
// K3: u = v/sig2 + W(y - z/sig2);  w = Q(Q^T u). one block per bin.
// ===========================================================================
__global__ void k_uw(const float* __restrict__ v, const float* __restrict__ Q_p) {
    __shared__ double sQ[32][17];
    __shared__ double sWl[32][17];
    __shared__ double sc[32];
    __shared__ double su[64];
    __shared__ double st[32];

    int tid = threadIdx.x;     // 64: n*2+d
    int b = blockIdx.x;
    double isig2 = 1.0 / g_sig2;

    for (int i = tid; i < 512; i += 64) {
        sQ[i >> 4][i & 15]  = (double)Q_p[i];
        sWl[i >> 4][i & 15] = g_W[i];
    }
    if (tid < 32) {
        int m = tid >> 1, d = tid & 1;
        sc[tid] = g_y[m * 200 + b * 2 + d] - g_z[b * 32 + m * 2 + d] * isig2;
    }
    __syncthreads();
    {
        int n = tid >> 1, d = tid & 1;
        double acc = (double)v[b * 64 + tid] * isig2;
        for (int m = 0; m < 16; ++m) acc += sWl[n][m] * sc[m * 2 + d];
        su[tid] = acc;
    }
    __syncthreads();
    if (tid < 32) {
        int k = tid >> 1, d = tid & 1;
        double acc = 0.0;
        for (int n = 0; n < 32; ++n) acc += sQ[n][k] * su[n * 2 + d];
        st[tid] = acc;
    }
    __syncthreads();
    {
        int n = tid >> 1, d = tid & 1;
        double acc = 0.0;
        for (int k = 0; k < 16; ++k) acc += sQ[n][k] * st[k * 2 + d];
        g_wf[b * 64 + tid] = (float)acc;
    }
}

// ===========================================================================
// K4 (fp32): pred_v[t] = sum_b RBF(ts[t],c_b) * w[b]; xt = x_last + (ts-1)*pred_v
// ===========================================================================
__global__ void k_pred(const float* __restrict__ ls_p) {
    __shared__ float sB[BINS];
    __shared__ float sxl[64];
    int tid = threadIdx.x;   // 128
    int t = blockIdx.x;
    float ls = ls_p[0];
    float inv2ls2 = 0.5f / (ls * ls);
    float dt_off = (float)t / 99.0f;
    float tt = 1.0f + dt_off;

    if (tid < BINS) {
        float d = tt - ((float)tid + 0.5f) * 0.01f;
        sB[tid] = expf(-d * d * inv2ls2);
    }
    if (tid < 64) sxl[tid] = (float)g_xlast[tid];
    __syncthreads();
    if (tid < 64) {
        float acc = 0.0f;
        for (int b = 0; b < BINS; ++b) acc = fmaf(sB[b], g_wf[b * 64 + tid], acc);
        g_xtf[t * 64 + tid] = sxl[tid] + dt_off * acc;
    }
}

// ===========================================================================
// K5 (fp32): lambda[n][m] = dt * sum_t exp(beta_n + beta_m - dist_t(n,m))
// ===========================================================================
__global__ void k_lam(const float* __restrict__ beta_p, float* __restrict__ out) {
    __shared__ float sb[32];
    int tid = threadIdx.x;     // 32
    int n = blockIdx.x;        // 32 blocks
    sb[tid] = beta_p[tid];
    __syncwarp();
    float bsum = sb[n] + sb[tid];
    const float2* xt2 = (const float2*)g_xtf;
    float acc = 0.0f;
    for (int t = 0; t < TT; ++t) {
        float2 a = xt2[t * 32 + n];
        float2 c = xt2[t * 32 + tid];
        float dx = a.x - c.x, dy = a.y - c.y;
        float sq = fmaf(dx, dx, dy * dy);
        sq = fmaxf(sq, 1e-12f);
        acc += expf(bsum - sqrtf(sq));
    }
    out[n * 32 + tid] = acc * (1.0f / 99.0f);
}

extern "C" void kernel_launch(void* const* d_in, const int* in_sizes, int n_in,
                              void* d_out, int out_size) {
    const float* x0    = (const float*)d_in[0];
    const float* v     = (const float*)d_in[1];
    const float* beta  = (const float*)d_in[2];
    const float* sigma = (const float*)d_in[3];
    // d_in[4] = prior_B_x0_c: x0 block provably never reaches output.
    const float* ls    = (const float*)d_in[5];
    const float* Q     = (const float*)d_in[6];
    float* out = (float*)d_out;

    const int chol_smem = (BINS * LDA + 3 * BINS) * (int)sizeof(double);  // 83200
    cudaFuncSetAttribute(k_chol, cudaFuncAttributeMaxDynamicSharedMemorySize, chol_smem);

    k_prep<<<1, 256>>>(x0, v, sigma, ls, Q);
    k_chol<<<16, 128, chol_smem>>>();
    k_uw<<<BINS, 64>>>(v, Q);
    k_pred<<<TT, 128>>>(ls);
    k_lam<<<32, 32>>>(beta, out);
}

// round 11
// speedup vs baseline: 2.2940x; 1.1041x over previous
#include <cuda_runtime.h>
#include <math.h>

#define NN 32
#define KK 16
#define BINS 100
#define TT 99
#define LDA 101   // padded leading dim

// ---- device scratch ----
__device__ double g_T[BINS];            // Toeplitz row of A1 (no jitter)
__device__ double g_W[NN * KK];         // orthonormal eigenbasis of QQ^T
__device__ double g_z[BINS * KK * 2];   // z[b][m][d]
__device__ double g_s2[KK];             // eigenvalues of Q^T Q
__device__ double g_sig2;
__device__ double g_xlast[NN * 2];
__device__ double g_y[KK * BINS * 2];   // y[m][b][d]
__device__ float  g_wf[BINS * NN * 2];  // w = QQ^T u (fp32 tail)
__device__ float  g_xtf[TT * NN * 2];   // xt[t][n][d] fp32

// fp64 rsqrt: fp32 seed + 1 fp64 Newton (rel err ~2e-8)
__device__ __forceinline__ double drsqrt1(double x) {
    double y = (double)rsqrtf((float)x);
    y = y * fma(-0.5 * x * y, y, 1.5);
    return y;
}
// fp64 reciprocal: fp32 fast-div seed + 1 fp64 Newton (rel err ~1e-13)
__device__ __forceinline__ double drcp1(double x) {
    double y = (double)__fdividef(1.0f, (float)x);
    y = y * fma(-x, y, 2.0);
    return y;
}

// ===========================================================================
// K1: Toeplitz row, G = Q^T Q, Jacobi eigen (fp32 c/s, 6 sweeps), W, z, x_last
// ===========================================================================
__global__ void k_prep(const float* __restrict__ x0, const float* __restrict__ v,
                       const float* __restrict__ sigma_p, const float* __restrict__ ls_p,
                       const float* __restrict__ Q_p) {
    __shared__ double sG[16][17];
    __shared__ double sV[16][17];
    __shared__ double sQ[32][17];
    __shared__ double sW[32][17];
    __shared__ double sC[8], sS[8];
    __shared__ int sP[8], sQn[8];

    int tid = threadIdx.x;     // 256
    double ls = (double)ls_p[0];
    double inv2ls2 = 0.5 / (ls * ls);

    if (tid < BINS) {
        double d = (double)tid * 0.01;
        g_T[tid] = exp(-d * d * inv2ls2);
    }
    for (int i = tid; i < 512; i += 256) sQ[i >> 4][i & 15] = (double)Q_p[i];
    if (tid == 0) {
        double s = (double)sigma_p[0];
        if (s < 0.05) s = 0.05;
        g_sig2 = s * s;
    }
    __syncthreads();

    {   // G = Q^T Q, V = I
        int i = tid >> 4, j = tid & 15;
        double acc = 0.0;
        for (int n = 0; n < 32; ++n) acc += sQ[n][i] * sQ[n][j];
        sG[i][j] = acc;
        sV[i][j] = (i == j) ? 1.0 : 0.0;
    }
    __syncthreads();

    // cyclic Jacobi: static round-robin, 6 sweeps x 15 rounds x 8 pairs.
    // c,s computed fully in fp32 (non-orthogonality ~1e-7/rot -> ~2e-5 eigen drift).
    for (int sweep = 0; sweep < 6; ++sweep) {
        for (int r = 0; r < 15; ++r) {
            if (tid < 8) {
                int p, q;
                if (tid == 0) { p = 15; q = r; }
                else { p = (r + tid) % 15; q = (r + 15 - tid) % 15; }
                if (p > q) { int t = p; p = q; q = t; }
                sP[tid] = p; sQn[tid] = q;
                double app = sG[p][p], aqq = sG[q][q], apq = sG[p][q];
                double c = 1.0, s = 0.0;
                if (fabs(apq) > 1e-25) {
                    float tauf = __fdividef((float)(aqq - app), 2.0f * (float)apq);
                    float tf = copysignf(1.0f, tauf) /
                               (fabsf(tauf) + sqrtf(fmaf(tauf, tauf, 1.0f)));
                    float cf = rsqrtf(fmaf(tf, tf, 1.0f));
                    c = (double)cf;
                    s = (double)(tf * cf);
                }
                sC[tid] = c; sS[tid] = s;
            }
            __syncthreads();
            if (tid < 128) {                       // column rotation on G
                int rr = tid >> 4, i = tid & 15;
                int p = sP[rr], q = sQn[rr]; double c = sC[rr], s = sS[rr];
                double gp = sG[i][p], gq = sG[i][q];
                sG[i][p] = c * gp - s * gq; sG[i][q] = s * gp + c * gq;
            } else {                               // V <- V*J (independent)
                int rr = (tid - 128) >> 4, i = (tid - 128) & 15;
                int p = sP[rr], q = sQn[rr]; double c = sC[rr], s = sS[rr];
                double gp = sV[i][p], gq = sV[i][q];
                sV[i][p] = c * gp - s * gq; sV[i][q] = s * gp + c * gq;
            }
            __syncthreads();
            if (tid < 128) {                       // row rotation on G
                int rr = tid >> 4, i = tid & 15;
                int p = sP[rr], q = sQn[rr]; double c = sC[rr], s = sS[rr];
                double gp = sG[p][i], gq = sG[q][i];
                sG[p][i] = c * gp - s * gq; sG[q][i] = s * gp + c * gq;
            }
            __syncthreads();
        }
    }

    if (tid < 16) {
        double e = sG[tid][tid];
        g_s2[tid] = (e > 0.0) ? e : 0.0;
    }

    // W = Q * V * S^-1
    for (int o = tid; o < 512; o += 256) {
        int n = o >> 4, m = o & 15;
        double acc = 0.0;
        for (int k = 0; k < 16; ++k) acc += sQ[n][k] * sV[k][m];
        double e = sG[m][m]; if (e < 1e-30) e = 1e-30;
        double w = acc * drsqrt1(e);
        sW[n][m] = w;
        g_W[o] = w;
    }
    __syncthreads();

    // z[b][m][d] = sum_n W[n][m] * v[b][n][d]
    for (int o = tid; o < BINS * KK * 2; o += 256) {
        int b = o >> 5, rem = o & 31, m = rem >> 1, d = rem & 1;
        const float* vb = v + b * 64;
        double acc = 0.0;
        for (int n = 0; n < 32; ++n) acc += sW[n][m] * (double)vb[n * 2 + d];
        g_z[o] = acc;
    }

    // x_last = x0 + (1/BINS) * sum_b v
    if (tid < 64) {
        double acc = 0.0;
        for (int b = 0; b < BINS; ++b) acc += (double)v[b * 64 + tid];
        g_xlast[tid] = (double)x0[tid] + 0.01 * acc;
    }
}

// ===========================================================================
// K2: per-mode LDL^T of (sigma^2 I + s2_m A1): 1 barrier/step, lookahead dinv,
//     register-resident warp solves via shfl (fully unrolled).
// ===========================================================================
__global__ void k_chol() {
    extern __shared__ double sm[];
    double* M    = sm;                  // 100 x 101
    double* dinv = sm + BINS * LDA;     // 100
    double* yv   = dinv + BINS;         // 2 x 100
    __shared__ double sT[BINS];

    int tid = threadIdx.x;              // 128
    int m = blockIdx.x;
    double s2 = g_s2[m];
    double sig2 = g_sig2;

    if (tid < BINS) sT[tid] = g_T[tid];
    __syncthreads();
    double dval = s2 * (sT[0] + 1e-5) + sig2;   // jitter folded into diagonal
    for (int idx = tid; idx < BINS * BINS; idx += 128) {
        int i = idx / BINS, j = idx - i * BINS;
        int dd = i - j; if (dd < 0) dd = -dd;
        M[i * LDA + j] = (dd == 0) ? dval : s2 * sT[dd];
    }
    if (tid < BINS) {
        yv[tid]        = g_z[tid * 32 + m * 2];
        yv[BINS + tid] = g_z[tid * 32 + m * 2 + 1];
    }
    if (tid == 0) dinv[0] = drcp1(dval);
    __syncthreads();

    // LDL^T (lower, unit L implicit; M keeps raw columns = L*d).
    // tid 0 finalizes M[k+1][k+1] and dinv[k+1] inside the step (lookahead).
    for (int k = 0; k < BINS - 1; ++k) {
        double dk = dinv[k];
        if (tid == 0) {
            double mk1 = M[(k + 1) * LDA + k];
            double nv = fma(-mk1, mk1 * dk, M[(k + 1) * LDA + (k + 1)]);
            M[(k + 1) * LDA + (k + 1)] = nv;
            dinv[k + 1] = drcp1(nv);
        }
        int ty = tid >> 4, tx = tid & 15;
        for (int j = k + 1 + ty; j < BINS; j += 8) {
            double t = M[j * LDA + k] * dk;
            int ibeg = j + tx;
            if (tid == 0 && j == k + 1) ibeg += 16;   // diag already done above
            for (int i = ibeg; i < BINS; i += 16)
                M[i * LDA + j] = fma(-M[i * LDA + k], t, M[i * LDA + j]);
        }
        __syncthreads();
    }

    // scale strict lower triangle in place: L[i][j] = M[i][j] * dinv[j]
    for (int idx = tid; idx < BINS * BINS; idx += 128) {
        int i = idx / BINS, j = idx - i * BINS;
        if (i > j) M[i * LDA + j] *= dinv[j];
    }
    __syncthreads();

    // warp-level solves: warp 0 -> rhs d=0, warp 1 -> rhs d=1. y in registers.
    int w = tid >> 5, lane = tid & 31;
    if (w < 2) {
        const double* Y = yv + w * BINS;
        double yr[4];
        #pragma unroll
        for (int s = 0; s < 4; ++s) {
            int i = 32 * s + lane;
            yr[s] = (i < BINS) ? Y[i] : 0.0;
        }
        // forward: c = L^{-1} z   (unit L)
        #pragma unroll
        for (int k = 0; k < BINS; ++k) {
            double ck = __shfl_sync(0xffffffffu, yr[k >> 5], k & 31);
            #pragma unroll
            for (int s = 0; s < 4; ++s) {
                int i = 32 * s + lane;
                if (i > k && i < BINS)
                    yr[s] = fma(-M[i * LDA + k], ck, yr[s]);
            }
        }
        // e = D^-1 c
        #pragma unroll
        for (int s = 0; s < 4; ++s) {
            int i = 32 * s + lane;
            if (i < BINS) yr[s] *= dinv[i];
        }
        // backward: x = L^-T e
        #pragma unroll
        for (int k = BINS - 1; k >= 0; --k) {
            double xk = __shfl_sync(0xffffffffu, yr[k >> 5], k & 31);
            #pragma unroll
            for (int s = 0; s < 4; ++s) {
                int i = 32 * s + lane;
                if (i < k)
                    yr[s] = fma(-M[k * LDA + i], xk, yr[s]);
            }
        }
        #pragma unroll
        for (int s = 0; s < 4; ++s) {
            int i = 32 * s + lane;
            if (i < BINS) g_y[m * 200 + i * 2 + w] = yr[s];
        }
    }
}

// ===========================================================================
// K3: u = v/sig2 + W(y - z/sig2);  w = Q(Q^T u). one block per bin.
// ===========================================================================
__global__ void k_uw(const float* __restrict__ v, const float* __restrict__ Q_p) {
    __shared__ double sQ[32][17];
    __shared__ double sWl[32][17];
    __shared__ double sc[32];
    __shared__ double su[64];
    __shared__ double st[32];

    int tid = threadIdx.x;     // 64: n*2+d
    int b = blockIdx.x;
    double isig2 = 1.0 / g_sig2;

    for (int i = tid; i < 512; i += 64) {
        sQ[i >> 4][i & 15]  = (double)Q_p[i];
        sWl[i >> 4][i & 15] = g_W[i];
    }
    if (tid < 32) {
        int m = tid >> 1, d = tid & 1;
        sc[tid] = g_y[m * 200 + b * 2 + d] - g_z[b * 32 + m * 2 + d] * isig2;
    }
    __syncthreads();
    {
        int n = tid >> 1, d = tid & 1;
        double acc = (double)v[b * 64 + tid] * isig2;
        for (int m = 0; m < 16; ++m) acc += sWl[n][m] * sc[m * 2 + d];
        su[tid] = acc;
    }
    __syncthreads();
    if (tid < 32) {
        int k = tid >> 1, d = tid & 1;
        double acc = 0.0;
        for (int n = 0; n < 32; ++n) acc += sQ[n][k] * su[n * 2 + d];
        st[tid] = acc;
    }
    __syncthreads();
    {
        int n = tid >> 1, d = tid & 1;
        double acc = 0.0;
        for (int k = 0; k < 16; ++k) acc += sQ[n][k] * st[k * 2 + d];
        g_wf[b * 64 + tid] = (float)acc;
    }
}

// ===========================================================================
// K4 (fp32): pred_v[t] = sum_b RBF(ts[t],c_b) * w[b]; xt = x_last + (ts-1)*pred_v
// ===========================================================================
__global__ void k_pred(const float* __restrict__ ls_p) {
    __shared__ float sB[BINS];
    __shared__ float sxl[64];
    int tid = threadIdx.x;   // 128
    int t = blockIdx.x;
    float ls = ls_p[0];
    float inv2ls2 = 0.5f / (ls * ls);
    float dt_off = (float)t / 99.0f;
    float tt = 1.0f + dt_off;

    if (tid < BINS) {
        float d = tt - ((float)tid + 0.5f) * 0.01f;
        sB[tid] = expf(-d * d * inv2ls2);
    }
    if (tid < 64) sxl[tid] = (float)g_xlast[tid];
    __syncthreads();
    if (tid < 64) {
        float acc = 0.0f;
        for (int b = 0; b < BINS; ++b) acc = fmaf(sB[b], g_wf[b * 64 + tid], acc);
        g_xtf[t * 64 + tid] = sxl[tid] + dt_off * acc;
    }
}

// ===========================================================================
// K5 (fp32): lambda[n][m] = dt * sum_t exp(beta_n + beta_m - dist_t(n,m))
// ===========================================================================
__global__ void k_lam(const float* __restrict__ beta_p, float* __restrict__ out) {
    __shared__ float sb[32];
    int tid = threadIdx.x;     // 32
    int n = blockIdx.x;        // 32 blocks
    sb[tid] = beta_p[tid];
    __syncwarp();
    float bsum = sb[n] + sb[tid];
    const float2* xt2 = (const float2*)g_xtf;
    float acc = 0.0f;
    for (int t = 0; t < TT; ++t) {
        float2 a = xt2[t * 32 + n];
        float2 c = xt2[t * 32 + tid];
        float dx = a.x - c.x, dy = a.y - c.y;
        float sq = fmaf(dx, dx, dy * dy);
        sq = fmaxf(sq, 1e-12f);
        acc += expf(bsum - sqrtf(sq));
    }
    out[n * 32 + tid] = acc * (1.0f / 99.0f);
}

extern "C" void kernel_launch(void* const* d_in, const int* in_sizes, int n_in,
                              void* d_out, int out_size) {
    const float* x0    = (const float*)d_in[0];
    const float* v     = (const float*)d_in[1];
    const float* beta  = (const float*)d_in[2];
    const float* sigma = (const float*)d_in[3];
    // d_in[4] = prior_B_x0_c: x0 block provably never reaches output.
    const float* ls    = (const float*)d_in[5];
    const float* Q     = (const float*)d_in[6];
    float* out = (float*)d_out;

    const int chol_smem = (BINS * LDA + 3 * BINS) * (int)sizeof(double);  // 83200
    cudaFuncSetAttribute(k_chol, cudaFuncAttributeMaxDynamicSharedMemorySize, chol_smem);

    k_prep<<<1, 256>>>(x0, v, sigma, ls, Q);
    k_chol<<<16, 128, chol_smem>>>();
    k_uw<<<BINS, 64>>>(v, Q);
    k_pred<<<TT, 128>>>(ls);
    k_lam<<<32, 32>>>(beta, out);
}

// round 15
// speedup vs baseline: 3.0872x; 1.3458x over previous
#include <cuda_runtime.h>
#include <math.h>

#define NN 32
#define KK 16
#define BINS 100
#define TT 99
#define LDA 101   // padded leading dim

// ---- device scratch ----
__device__ double g_W[NN * KK];         // orthonormal eigenbasis of QQ^T
__device__ double g_z[BINS * KK * 2];   // z[b][m][d]
__device__ double g_sig2;
__device__ double g_xlast[NN * 2];
__device__ double g_y[KK * BINS * 2];   // y[m][b][d]
__device__ float  g_wf[BINS * NN * 2];  // w = QQ^T u (fp32 tail)
__device__ float  g_xtf[TT * NN * 2];   // xt[t][n][d] fp32

// fp64 rsqrt: fp32 seed + 1 fp64 Newton (rel err ~2e-8)
__device__ __forceinline__ double drsqrt1(double x) {
    double y = (double)rsqrtf((float)x);
    y = y * fma(-0.5 * x * y, y, 1.5);
    return y;
}
// fp64 reciprocal: fp32 fast-div seed + 1 fp64 Newton (rel err ~1e-13)
__device__ __forceinline__ double drcp1(double x) {
    double y = (double)__fdividef(1.0f, (float)x);
    y = y * fma(-x, y, 2.0);
    return y;
}

// ===========================================================================
// K_MAIN: 16 blocks x 256 threads. EACH block (mode m) redundantly computes:
//   Toeplitz row, G = Q^T Q, Jacobi eigen (fp32 c/s, 5 sweeps), W, its z_m;
// then factors (sigma^2 I + s2_m A1) via LDL^T and solves 2 RHS.
// Block 0 additionally publishes g_W, g_xlast, g_sig2 for the tail kernels.
// ===========================================================================
__global__ void k_main(const float* __restrict__ x0, const float* __restrict__ v,
                       const float* __restrict__ sigma_p, const float* __restrict__ ls_p,
                       const float* __restrict__ Q_p) {
    extern __shared__ double sm[];
    double* M    = sm;                  // 100 x 101
    double* dinv = sm + BINS * LDA;     // 100
    double* yv   = dinv + BINS;         // 2 x 100

    __shared__ double sG[16][17];
    __shared__ double sV[16][17];
    __shared__ double sQ[32][17];
    __shared__ double sW[32][17];
    __shared__ double sT[BINS];
    __shared__ double sz[BINS * 2];     // z_m[b][d]
    __shared__ double sC[8], sS[8];
    __shared__ int sP[8], sQn[8];

    int tid = threadIdx.x;              // 256
    int m = blockIdx.x;                 // mode
    double ls = (double)ls_p[0];
    double inv2ls2 = 0.5 / (ls * ls);
    double sigc = (double)sigma_p[0];
    if (sigc < 0.05) sigc = 0.05;
    double sig2 = sigc * sigc;

    if (tid < BINS) {
        double d = (double)tid * 0.01;
        sT[tid] = exp(-d * d * inv2ls2);
    }
    for (int i = tid; i < 512; i += 256) sQ[i >> 4][i & 15] = (double)Q_p[i];
    __syncthreads();

    {   // G = Q^T Q, V = I
        int i = tid >> 4, j = tid & 15;
        double acc = 0.0;
        for (int n = 0; n < 32; ++n) acc += sQ[n][i] * sQ[n][j];
        sG[i][j] = acc;
        sV[i][j] = (i == j) ? 1.0 : 0.0;
    }
    __syncthreads();

    // cyclic Jacobi: static round-robin, 5 sweeps x 15 rounds x 8 pairs; fp32 c/s
    for (int sweep = 0; sweep < 5; ++sweep) {
        for (int r = 0; r < 15; ++r) {
            if (tid < 8) {
                int p, q;
                if (tid == 0) { p = 15; q = r; }
                else { p = (r + tid) % 15; q = (r + 15 - tid) % 15; }
                if (p > q) { int t = p; p = q; q = t; }
                sP[tid] = p; sQn[tid] = q;
                double app = sG[p][p], aqq = sG[q][q], apq = sG[p][q];
                double c = 1.0, s = 0.0;
                if (fabs(apq) > 1e-25) {
                    float tauf = __fdividef((float)(aqq - app), 2.0f * (float)apq);
                    float tf = copysignf(1.0f, tauf) /
                               (fabsf(tauf) + sqrtf(fmaf(tauf, tauf, 1.0f)));
                    float cf = rsqrtf(fmaf(tf, tf, 1.0f));
                    c = (double)cf;
                    s = (double)(tf * cf);
                }
                sC[tid] = c; sS[tid] = s;
            }
            __syncthreads();
            if (tid < 128) {                       // column rotation on G
                int rr = tid >> 4, i = tid & 15;
                int p = sP[rr], q = sQn[rr]; double c = sC[rr], s = sS[rr];
                double gp = sG[i][p], gq = sG[i][q];
                sG[i][p] = c * gp - s * gq; sG[i][q] = s * gp + c * gq;
            } else {                               // V <- V*J (independent)
                int rr = (tid - 128) >> 4, i = (tid - 128) & 15;
                int p = sP[rr], q = sQn[rr]; double c = sC[rr], s = sS[rr];
                double gp = sV[i][p], gq = sV[i][q];
                sV[i][p] = c * gp - s * gq; sV[i][q] = s * gp + c * gq;
            }
            __syncthreads();
            if (tid < 128) {                       // row rotation on G
                int rr = tid >> 4, i = tid & 15;
                int p = sP[rr], q = sQn[rr]; double c = sC[rr], s = sS[rr];
                double gp = sG[p][i], gq = sG[q][i];
                sG[p][i] = c * gp - s * gq; sG[q][i] = s * gp + c * gq;
            }
            __syncthreads();
        }
    }

    // W = Q * V * S^-1 (full, for z_m and block-0 publish)
    for (int o = tid; o < 512; o += 256) {
        int n = o >> 4, mm = o & 15;
        double acc = 0.0;
        for (int k = 0; k < 16; ++k) acc += sQ[n][k] * sV[k][mm];
        double e = sG[mm][mm]; if (e < 1e-30) e = 1e-30;
        double w = acc * drsqrt1(e);
        sW[n][mm] = w;
        if (m == 0) g_W[o] = w;
    }
    __syncthreads();

    // z_m[b][d] = sum_n W[n][m] * v[b][n][d]; publish slice of g_z
    if (tid < BINS * 2) {
        int b = tid >> 1, d = tid & 1;
        const float* vb = v + b * 64;
        double acc = 0.0;
        for (int n = 0; n < 32; ++n) acc += sW[n][m] * (double)vb[n * 2 + d];
        sz[tid] = acc;
        g_z[b * 32 + m * 2 + d] = acc;
    }

    // block 0 extras: x_last, sig2
    if (m == 0) {
        if (tid >= 128 && tid < 192) {
            int o = tid - 128;
            double acc = 0.0;
            for (int b = 0; b < BINS; ++b) acc += (double)v[b * 64 + o];
            g_xlast[o] = (double)x0[o] + 0.01 * acc;
        }
        if (tid == 255) g_sig2 = sig2;
    }

    double s2 = sG[m][m]; if (s2 < 0.0) s2 = 0.0;   // eigenvalue for this mode
    __syncthreads();

    // build M = sigma^2 I + s2*(A1 + jitter I) from Toeplitz row
    double dval = s2 * (sT[0] + 1e-5) + sig2;
    for (int idx = tid; idx < BINS * BINS; idx += 256) {
        int i = idx / BINS, j = idx - i * BINS;
        int dd = i - j; if (dd < 0) dd = -dd;
        M[i * LDA + j] = (dd == 0) ? dval : s2 * sT[dd];
    }
    if (tid < BINS) {
        yv[tid]        = sz[tid * 2];
        yv[BINS + tid] = sz[tid * 2 + 1];
    }
    if (tid == 0) dinv[0] = drcp1(dval);
    __syncthreads();

    // LDL^T (lower, unit L implicit; M keeps raw columns = L*d).
    // tid 0 finalizes M[k+1][k+1] and dinv[k+1] inside the step (lookahead).
    for (int k = 0; k < BINS - 1; ++k) {
        double dk = dinv[k];
        if (tid == 0) {
            double mk1 = M[(k + 1) * LDA + k];
            double nv = fma(-mk1, mk1 * dk, M[(k + 1) * LDA + (k + 1)]);
            M[(k + 1) * LDA + (k + 1)] = nv;
            dinv[k + 1] = drcp1(nv);
        }
        int ty = tid >> 4, tx = tid & 15;
        for (int j = k + 1 + ty; j < BINS; j += 16) {
            double t = M[j * LDA + k] * dk;
            int ibeg = j + tx;
            if (tid == 0 && j == k + 1) ibeg += 16;   // diag already done above
            for (int i = ibeg; i < BINS; i += 16)
                M[i * LDA + j] = fma(-M[i * LDA + k], t, M[i * LDA + j]);
        }
        __syncthreads();
    }

    // scale strict lower triangle in place: L[i][j] = M[i][j] * dinv[j]
    for (int idx = tid; idx < BINS * BINS; idx += 256) {
        int i = idx / BINS, j = idx - i * BINS;
        if (i > j) M[i * LDA + j] *= dinv[j];
    }
    __syncthreads();

    // warp-level solves: warp 0 -> rhs d=0, warp 1 -> rhs d=1. y in registers.
    int w = tid >> 5, lane = tid & 31;
    if (w < 2) {
        const double* Y = yv + w * BINS;
        double yr[4];
        #pragma unroll
        for (int s = 0; s < 4; ++s) {
            int i = 32 * s + lane;
            yr[s] = (i < BINS) ? Y[i] : 0.0;
        }
        // forward: c = L^{-1} z   (unit L)
        #pragma unroll
        for (int k = 0; k < BINS; ++k) {
            double ck = __shfl_sync(0xffffffffu, yr[k >> 5], k & 31);
            #pragma unroll
            for (int s = 0; s < 4; ++s) {
                int i = 32 * s + lane;
                if (i > k && i < BINS)
                    yr[s] = fma(-M[i * LDA + k], ck, yr[s]);
            }
        }
        // e = D^-1 c
        #pragma unroll
        for (int s = 0; s < 4; ++s) {
            int i = 32 * s + lane;
            if (i < BINS) yr[s] *= dinv[i];
        }
        // backward: x = L^-T e
        #pragma unroll
        for (int k = BINS - 1; k >= 0; --k) {
            double xk = __shfl_sync(0xffffffffu, yr[k >> 5], k & 31);
            #pragma unroll
            for (int s = 0; s < 4; ++s) {
                int i = 32 * s + lane;
                if (i < k)
                    yr[s] = fma(-M[k * LDA + i], xk, yr[s]);
            }
        }
        #pragma unroll
        for (int s = 0; s < 4; ++s) {
            int i = 32 * s + lane;
            if (i < BINS) g_y[m * 200 + i * 2 + w] = yr[s];
        }
    }
}

// ===========================================================================
// K3: u = v/sig2 + W(y - z/sig2);  w = Q(Q^T u). one block per bin.
// ===========================================================================
__global__ void k_uw(const float* __restrict__ v, const float* __restrict__ Q_p) {
    __shared__ double sQ[32][17];
    __shared__ double sWl[32][17];
    __shared__ double sc[32];
    __shared__ double su[64];
    __shared__ double st[32];

    int tid = threadIdx.x;     // 64: n*2+d
    int b = blockIdx.x;
    double isig2 = 1.0 / g_sig2;

    for (int i = tid; i < 512; i += 64) {
        sQ[i >> 4][i & 15]  = (double)Q_p[i];
        sWl[i >> 4][i & 15] = g_W[i];
    }
    if (tid < 32) {
        int m = tid >> 1, d = tid & 1;
        sc[tid] = g_y[m * 200 + b * 2 + d] - g_z[b * 32 + m * 2 + d] * isig2;
    }
    __syncthreads();
    {
        int n = tid >> 1, d = tid & 1;
        double acc = (double)v[b * 64 + tid] * isig2;
        for (int m = 0; m < 16; ++m) acc += sWl[n][m] * sc[m * 2 + d];
        su[tid] = acc;
    }
    __syncthreads();
    if (tid < 32) {
        int k = tid >> 1, d = tid & 1;
        double acc = 0.0;
        for (int n = 0; n < 32; ++n) acc += sQ[n][k] * su[n * 2 + d];
        st[tid] = acc;
    }
    __syncthreads();
    {
        int n = tid >> 1, d = tid & 1;
        double acc = 0.0;
        for (int k = 0; k < 16; ++k) acc += sQ[n][k] * st[k * 2 + d];
        g_wf[b * 64 + tid] = (float)acc;
    }
}

// ===========================================================================
// K4 (fp32): pred_v[t] = sum_b RBF(ts[t],c_b) * w[b]; xt = x_last + (ts-1)*pred_v
// ===========================================================================
__global__ void k_pred(const float* __restrict__ ls_p) {
    __shared__ float sB[BINS];
    __shared__ float sxl[64];
    int tid = threadIdx.x;   // 128
    int t = blockIdx.x;
    float ls = ls_p[0];
    float inv2ls2 = 0.5f / (ls * ls);
    float dt_off = (float)t / 99.0f;
    float tt = 1.0f + dt_off;

    if (tid < BINS) {
        float d = tt - ((float)tid + 0.5f) * 0.01f;
        sB[tid] = expf(-d * d * inv2ls2);
    }
    if (tid < 64) sxl[tid] = (float)g_xlast[tid];
    __syncthreads();
    if (tid < 64) {
        float acc = 0.0f;
        for (int b = 0; b < BINS; ++b) acc = fmaf(sB[b], g_wf[b * 64 + tid], acc);
        g_xtf[t * 64 + tid] = sxl[tid] + dt_off * acc;
    }
}

// ===========================================================================
// K5 (fp32): lambda[n][m] = dt * sum_t exp(beta_n + beta_m - dist_t(n,m))
// ===========================================================================
__global__ void k_lam(const float* __restrict__ beta_p, float* __restrict__ out) {
    __shared__ float sb[32];
    int tid = threadIdx.x;     // 32
    int n = blockIdx.x;        // 32 blocks
    sb[tid] = beta_p[tid];
    __syncwarp();
    float bsum = sb[n] + sb[tid];
    const float2* xt2 = (const float2*)g_xtf;
    float acc = 0.0f;
    for (int t = 0; t < TT; ++t) {
        float2 a = xt2[t * 32 + n];
        float2 c = xt2[t * 32 + tid];
        float dx = a.x - c.x, dy = a.y - c.y;
        float sq = fmaf(dx, dx, dy * dy);
        sq = fmaxf(sq, 1e-12f);
        acc += expf(bsum - sqrtf(sq));
    }
    out[n * 32 + tid] = acc * (1.0f / 99.0f);
}

extern "C" void kernel_launch(void* const* d_in, const int* in_sizes, int n_in,
                              void* d_out, int out_size) {
    const float* x0    = (const float*)d_in[0];
    const float* v     = (const float*)d_in[1];
    const float* beta  = (const float*)d_in[2];
    const float* sigma = (const float*)d_in[3];
    // d_in[4] = prior_B_x0_c: x0 block provably never reaches output.
    const float* ls    = (const float*)d_in[5];
    const float* Q     = (const float*)d_in[6];
    float* out = (float*)d_out;

    const int main_smem = (BINS * LDA + 3 * BINS) * (int)sizeof(double);  // 83200
    cudaFuncSetAttribute(k_main, cudaFuncAttributeMaxDynamicSharedMemorySize, main_smem);

    k_main<<<16, 256, main_smem>>>(x0, v, sigma, ls, Q);
    k_uw<<<BINS, 64>>>(v, Q);
    k_pred<<<TT, 128>>>(ls);
    k_lam<<<32, 32>>>(beta, out);
}

// round 17
// speedup vs baseline: 3.7320x; 1.2088x over previous
#include <cuda_runtime.h>
#include <math.h>

#define NN 32
#define KK 16
#define BINS 100
#define TT 99
#define LDA 101   // padded leading dim

// ---- device scratch ----
__device__ double g_W[NN * KK];         // orthonormal eigenbasis of QQ^T
__device__ double g_z[BINS * KK * 2];   // z[b][m][d]
__device__ double g_sig2;
__device__ double g_xlast[NN * 2];
__device__ double g_y[KK * BINS * 2];   // y[m][b][d]
__device__ float  g_wf[BINS * NN * 2];  // w = QQ^T u (fp32 tail)
__device__ float  g_xtf[TT * NN * 2];   // xt[t][n][d] fp32

// fp64 rsqrt: fp32 seed + 1 fp64 Newton (rel err ~2e-8)
__device__ __forceinline__ double drsqrt1(double x) {
    double y = (double)rsqrtf((float)x);
    y = y * fma(-0.5 * x * y, y, 1.5);
    return y;
}
// fp64 reciprocal: fp32 fast-div seed + 1 fp64 Newton (rel err ~1e-13)
__device__ __forceinline__ double drcp1(double x) {
    double y = (double)__fdividef(1.0f, (float)x);
    y = y * fma(-x, y, 2.0);
    return y;
}

// ===========================================================================
// K_MAIN: 16 blocks x 256 threads. EACH block (mode m) redundantly computes:
//   Toeplitz row, G = Q^T Q, Jacobi eigen (fp32 c/s, 4 sweeps), W, its z_m;
// then factors (sigma^2 I + s2_m A1) via LDL^T and solves 2 RHS.
// Block 0 additionally publishes g_W, g_xlast, g_sig2 for the tail kernels.
// ===========================================================================
__global__ void k_main(const float* __restrict__ x0, const float* __restrict__ v,
                       const float* __restrict__ sigma_p, const float* __restrict__ ls_p,
                       const float* __restrict__ Q_p) {
    extern __shared__ double sm[];
    double* M    = sm;                  // 100 x 101
    double* dinv = sm + BINS * LDA;     // 100
    double* yv   = dinv + BINS;         // 2 x 100

    __shared__ double sG[16][17];
    __shared__ double sV[16][17];
    __shared__ double sQ[32][17];
    __shared__ double sW[32][17];
    __shared__ double sT[BINS];
    __shared__ double sz[BINS * 2];     // z_m[b][d]
    __shared__ double sC[8], sS[8];
    __shared__ int sP[8], sQn[8];

    int tid = threadIdx.x;              // 256
    int m = blockIdx.x;                 // mode
    double ls = (double)ls_p[0];
    double inv2ls2 = 0.5 / (ls * ls);
    double sigc = (double)sigma_p[0];
    if (sigc < 0.05) sigc = 0.05;
    double sig2 = sigc * sigc;

    if (tid < BINS) {
        double d = (double)tid * 0.01;
        sT[tid] = exp(-d * d * inv2ls2);
    }
    for (int i = tid; i < 512; i += 256) sQ[i >> 4][i & 15] = (double)Q_p[i];
    __syncthreads();

    {   // G = Q^T Q, V = I
        int i = tid >> 4, j = tid & 15;
        double acc = 0.0;
        for (int n = 0; n < 32; ++n) acc += sQ[n][i] * sQ[n][j];
        sG[i][j] = acc;
        sV[i][j] = (i == j) ? 1.0 : 0.0;
    }
    __syncthreads();

    // cyclic Jacobi: static round-robin, 4 sweeps x 15 rounds x 8 pairs; fp32 c/s
    for (int sweep = 0; sweep < 4; ++sweep) {
        for (int r = 0; r < 15; ++r) {
            if (tid < 8) {
                int p, q;
                if (tid == 0) { p = 15; q = r; }
                else { p = (r + tid) % 15; q = (r + 15 - tid) % 15; }
                if (p > q) { int t = p; p = q; q = t; }
                sP[tid] = p; sQn[tid] = q;
                double app = sG[p][p], aqq = sG[q][q], apq = sG[p][q];
                double c = 1.0, s = 0.0;
                if (fabs(apq) > 1e-25) {
                    float tauf = __fdividef((float)(aqq - app), 2.0f * (float)apq);
                    float tf = copysignf(1.0f, tauf) /
                               (fabsf(tauf) + sqrtf(fmaf(tauf, tauf, 1.0f)));
                    float cf = rsqrtf(fmaf(tf, tf, 1.0f));
                    c = (double)cf;
                    s = (double)(tf * cf);
                }
                sC[tid] = c; sS[tid] = s;
            }
            __syncthreads();
            if (tid < 128) {                       // column rotation on G
                int rr = tid >> 4, i = tid & 15;
                int p = sP[rr], q = sQn[rr]; double c = sC[rr], s = sS[rr];
                double gp = sG[i][p], gq = sG[i][q];
                sG[i][p] = c * gp - s * gq; sG[i][q] = s * gp + c * gq;
            } else {                               // V <- V*J (independent)
                int rr = (tid - 128) >> 4, i = (tid - 128) & 15;
                int p = sP[rr], q = sQn[rr]; double c = sC[rr], s = sS[rr];
                double gp = sV[i][p], gq = sV[i][q];
                sV[i][p] = c * gp - s * gq; sV[i][q] = s * gp + c * gq;
            }
            __syncthreads();
            if (tid < 128) {                       // row rotation on G
                int rr = tid >> 4, i = tid & 15;
                int p = sP[rr], q = sQn[rr]; double c = sC[rr], s = sS[rr];
                double gp = sG[p][i], gq = sG[q][i];
                sG[p][i] = c * gp - s * gq; sG[q][i] = s * gp + c * gq;
            }
            __syncthreads();
        }
    }

    // W = Q * V * S^-1 (full, for z_m and block-0 publish)
    for (int o = tid; o < 512; o += 256) {
        int n = o >> 4, mm = o & 15;
        double acc = 0.0;
        for (int k = 0; k < 16; ++k) acc += sQ[n][k] * sV[k][mm];
        double e = sG[mm][mm]; if (e < 1e-30) e = 1e-30;
        double w = acc * drsqrt1(e);
        sW[n][mm] = w;
        if (m == 0) g_W[o] = w;
    }
    __syncthreads();

    // z_m[b][d] = sum_n W[n][m] * v[b][n][d]; publish slice of g_z
    if (tid < BINS * 2) {
        int b = tid >> 1, d = tid & 1;
        const float* vb = v + b * 64;
        double acc = 0.0;
        for (int n = 0; n < 32; ++n) acc += sW[n][m] * (double)vb[n * 2 + d];
        sz[tid] = acc;
        g_z[b * 32 + m * 2 + d] = acc;
    }

    // block 0 extras: x_last, sig2
    if (m == 0) {
        if (tid >= 128 && tid < 192) {
            int o = tid - 128;
            double acc = 0.0;
            for (int b = 0; b < BINS; ++b) acc += (double)v[b * 64 + o];
            g_xlast[o] = (double)x0[o] + 0.01 * acc;
        }
        if (tid == 255) g_sig2 = sig2;
    }

    double s2 = sG[m][m]; if (s2 < 0.0) s2 = 0.0;   // eigenvalue for this mode
    __syncthreads();

    // build M = sigma^2 I + s2*(A1 + jitter I) from Toeplitz row
    double dval = s2 * (sT[0] + 1e-5) + sig2;
    for (int idx = tid; idx < BINS * BINS; idx += 256) {
        int i = idx / BINS, j = idx - i * BINS;
        int dd = i - j; if (dd < 0) dd = -dd;
        M[i * LDA + j] = (dd == 0) ? dval : s2 * sT[dd];
    }
    if (tid < BINS) {
        yv[tid]        = sz[tid * 2];
        yv[BINS + tid] = sz[tid * 2 + 1];
    }
    if (tid == 0) dinv[0] = drcp1(dval);
    __syncthreads();

    // LDL^T (lower, unit L implicit; M keeps raw columns = L*d).
    // tid 0 finalizes M[k+1][k+1] and dinv[k+1] inside the step (lookahead).
    for (int k = 0; k < BINS - 1; ++k) {
        double dk = dinv[k];
        if (tid == 0) {
            double mk1 = M[(k + 1) * LDA + k];
            double nv = fma(-mk1, mk1 * dk, M[(k + 1) * LDA + (k + 1)]);
            M[(k + 1) * LDA + (k + 1)] = nv;
            dinv[k + 1] = drcp1(nv);
        }
        int ty = tid >> 4, tx = tid & 15;
        for (int j = k + 1 + ty; j < BINS; j += 16) {
            double t = M[j * LDA + k] * dk;
            int ibeg = j + tx;
            if (tid == 0 && j == k + 1) ibeg += 16;   // diag already done above
            for (int i = ibeg; i < BINS; i += 16)
                M[i * LDA + j] = fma(-M[i * LDA + k], t, M[i * LDA + j]);
        }
        __syncthreads();
    }

    // scale strict lower triangle in place: L[i][j] = M[i][j] * dinv[j]
    for (int idx = tid; idx < BINS * BINS; idx += 256) {
        int i = idx / BINS, j = idx - i * BINS;
        if (i > j) M[i * LDA + j] *= dinv[j];
    }
    __syncthreads();

    // warp-level solves: warp 0 -> rhs d=0, warp 1 -> rhs d=1. y in registers.
    int w = tid >> 5, lane = tid & 31;
    if (w < 2) {
        const double* Y = yv + w * BINS;
        double yr[4];
        #pragma unroll
        for (int s = 0; s < 4; ++s) {
            int i = 32 * s + lane;
            yr[s] = (i < BINS) ? Y[i] : 0.0;
        }
        // forward: c = L^{-1} z   (unit L)
        #pragma unroll
        for (int k = 0; k < BINS; ++k) {
            double ck = __shfl_sync(0xffffffffu, yr[k >> 5], k & 31);
            #pragma unroll
            for (int s = 0; s < 4; ++s) {
                int i = 32 * s + lane;
                if (i > k && i < BINS)
                    yr[s] = fma(-M[i * LDA + k], ck, yr[s]);
            }
        }
        // e = D^-1 c
        #pragma unroll
        for (int s = 0; s < 4; ++s) {
            int i = 32 * s + lane;
            if (i < BINS) yr[s] *= dinv[i];
        }
        // backward: x = L^-T e
        #pragma unroll
        for (int k = BINS - 1; k >= 0; --k) {
            double xk = __shfl_sync(0xffffffffu, yr[k >> 5], k & 31);
            #pragma unroll
            for (int s = 0; s < 4; ++s) {
                int i = 32 * s + lane;
                if (i < k)
                    yr[s] = fma(-M[k * LDA + i], xk, yr[s]);
            }
        }
        #pragma unroll
        for (int s = 0; s < 4; ++s) {
            int i = 32 * s + lane;
            if (i < BINS) g_y[m * 200 + i * 2 + w] = yr[s];
        }
    }
}

// ===========================================================================
// K3: u = v/sig2 + W(y - z/sig2);  w = Q(Q^T u). one block per bin.
// ===========================================================================
__global__ void k_uw(const float* __restrict__ v, const float* __restrict__ Q_p) {
    __shared__ double sQ[32][17];
    __shared__ double sWl[32][17];
    __shared__ double sc[32];
    __shared__ double su[64];
    __shared__ double st[32];

    int tid = threadIdx.x;     // 64: n*2+d
    int b = blockIdx.x;
    double isig2 = 1.0 / g_sig2;

    for (int i = tid; i < 512; i += 64) {
        sQ[i >> 4][i & 15]  = (double)Q_p[i];
        sWl[i >> 4][i & 15] = g_W[i];
    }
    if (tid < 32) {
        int m = tid >> 1, d = tid & 1;
        sc[tid] = g_y[m * 200 + b * 2 + d] - g_z[b * 32 + m * 2 + d] * isig2;
    }
    __syncthreads();
    {
        int n = tid >> 1, d = tid & 1;
        double acc = (double)v[b * 64 + tid] * isig2;
        for (int m = 0; m < 16; ++m) acc += sWl[n][m] * sc[m * 2 + d];
        su[tid] = acc;
    }
    __syncthreads();
    if (tid < 32) {
        int k = tid >> 1, d = tid & 1;
        double acc = 0.0;
        for (int n = 0; n < 32; ++n) acc += sQ[n][k] * su[n * 2 + d];
        st[tid] = acc;
    }
    __syncthreads();
    {
        int n = tid >> 1, d = tid & 1;
        double acc = 0.0;
        for (int k = 0; k < 16; ++k) acc += sQ[n][k] * st[k * 2 + d];
        g_wf[b * 64 + tid] = (float)acc;
    }
}

// ===========================================================================
// K4 (fp32): pred_v[t] = sum_b RBF(ts[t],c_b) * w[b]; xt = x_last + (ts-1)*pred_v
// ===========================================================================
__global__ void k_pred(const float* __restrict__ ls_p) {
    __shared__ float sB[BINS];
    __shared__ float sxl[64];
    int tid = threadIdx.x;   // 128
    int t = blockIdx.x;
    float ls = ls_p[0];
    float inv2ls2 = 0.5f / (ls * ls);
    float dt_off = (float)t / 99.0f;
    float tt = 1.0f + dt_off;

    if (tid < BINS) {
        float d = tt - ((float)tid + 0.5f) * 0.01f;
        sB[tid] = expf(-d * d * inv2ls2);
    }
    if (tid < 64) sxl[tid] = (float)g_xlast[tid];
    __syncthreads();
    if (tid < 64) {
        float acc = 0.0f;
        for (int b = 0; b < BINS; ++b) acc = fmaf(sB[b], g_wf[b * 64 + tid], acc);
        g_xtf[t * 64 + tid] = sxl[tid] + dt_off * acc;
    }
}

// ===========================================================================
// K5 (fp32): lambda[n][:] per block; 4 warps split the t-loop, xt staged in smem.
// Deterministic fixed-order reduction of the 4 partials.
// ===========================================================================
__global__ void k_lam(const float* __restrict__ beta_p, float* __restrict__ out) {
    __shared__ float2 sxt[TT * 32];      // 99*32 float2 = 25344 B
    __shared__ float  sb[32];
    __shared__ float  part[4][32];

    int tid = threadIdx.x;               // 128
    int w = tid >> 5, lane = tid & 31;
    int n = blockIdx.x;                  // 32 blocks

    const float2* xt2 = (const float2*)g_xtf;
    for (int i = tid; i < TT * 32; i += 128) sxt[i] = xt2[i];
    if (tid < 32) sb[tid] = beta_p[tid];
    __syncthreads();

    float bsum = sb[n] + sb[lane];
    float acc = 0.0f;
    for (int t = w; t < TT; t += 4) {
        float2 a = sxt[t * 32 + n];      // broadcast (same addr across lanes)
        float2 c = sxt[t * 32 + lane];
        float dx = a.x - c.x, dy = a.y - c.y;
        float sq = fmaf(dx, dx, dy * dy);
        sq = fmaxf(sq, 1e-12f);
        acc += expf(bsum - sqrtf(sq));
    }
    part[w][lane] = acc;
    __syncthreads();
    if (tid < 32) {
        float s = ((part[0][tid] + part[1][tid]) + part[2][tid]) + part[3][tid];
        out[n * 32 + tid] = s * (1.0f / 99.0f);
    }
}

extern "C" void kernel_launch(void* const* d_in, const int* in_sizes, int n_in,
                              void* d_out, int out_size) {
    const float* x0    = (const float*)d_in[0];
    const float* v     = (const float*)d_in[1];
    const float* beta  = (const float*)d_in[2];
    const float* sigma = (const float*)d_in[3];
    // d_in[4] = prior_B_x0_c: x0 block provably never reaches output.
    const float* ls    = (const float*)d_in[5];
    const float* Q     = (const float*)d_in[6];
    float* out = (float*)d_out;

    const int main_smem = (BINS * LDA + 3 * BINS) * (int)sizeof(double);  // 83200
    cudaFuncSetAttribute(k_main, cudaFuncAttributeMaxDynamicSharedMemorySize, main_smem);

    k_main<<<16, 256, main_smem>>>(x0, v, sigma, ls, Q);
    k_uw<<<BINS, 64>>>(v, Q);
    k_pred<<<TT, 128>>>(ls);
    k_lam<<<32, 128>>>(beta, out);
}